// round 14
// baseline (speedup 1.0000x reference)
#include <cuda_runtime.h>
#include <cuda_fp16.h>

// GCN 2-layer forward, fixed shape.
// Slot-bucketed aggregation, f32x2 GEMM, fp16 inter-layer features,
// fused epilogues, 8 threads/node agg, fused dinv+scale, graph-memset init,
// 2-stream overlap.
#define N_NODES 100000
#define N_EDGES 3200000
#define F_IN    512
#define HID     16
#define SLOT_CAP 128           // max degree capacity (Poisson(32), max~60)

// ---------------- device scratch (no allocations allowed) ----------------
__device__ int   g_is64;
__device__ int   g_cnt  [N_NODES];            // per-node incoming-edge count
__device__ int   g_slots[(size_t)N_NODES * SLOT_CAP]; // row ids per col bucket
__device__ float g_dinv [N_NODES];
__device__ __align__(16) __half2 g_ph [N_NODES * 8];  // layer-1 feats (8 half2/row)
__device__ __align__(16) __half2 g_ph2[N_NODES * 8];  // layer-2 feats

// ---------------- dtype detection (1 block, side stream) ------------------
__global__ void k_detect(const int* __restrict__ e) {
    // int64 little-endian values < 2^31 -> odd words all zero
    int odd = e[2 * threadIdx.x + 1];
    int any = __syncthreads_or(odd != 0);
    if (threadIdx.x == 0) g_is64 = !any;
}

// ---------------- slot fill: one pass, scalar per edge --------------------
__global__ void k_fill(const int* __restrict__ e) {
    int i = blockIdx.x * blockDim.x + threadIdx.x;
    if (i >= N_EDGES) return;
    int r, c;
    if (g_is64) {
        r = (int)((const long long*)e)[i];
        c = (int)((const long long*)e)[(long long)N_EDGES + i];
    } else {
        r = e[i];
        c = e[N_EDGES + i];
    }
    int pos = atomicAdd(&g_cnt[c], 1);
    if (pos < SLOT_CAP)
        g_slots[(size_t)c * SLOT_CAP + pos] = r;
}

// ---------------- GEMM1: ph = half(x @ W1) (unscaled), f32x2 FMA ----------
__device__ __forceinline__ void ffma2(unsigned long long& acc,
                                      unsigned long long a,
                                      unsigned long long b) {
    asm("fma.rn.f32x2 %0, %1, %2, %0;" : "+l"(acc) : "l"(a), "l"(b));
}

__device__ __forceinline__ unsigned long long bcast2(float x) {
    unsigned long long r;
    asm("mov.b64 %0, {%1, %1};" : "=l"(r) : "f"(x));
    return r;
}

__global__ __launch_bounds__(256) void k_gemm1(const float* __restrict__ x,
                                               const float* __restrict__ W1) {
    __shared__ float sW[F_IN * HID];   // 32 KB
    for (int i = threadIdx.x; i < (F_IN * HID) / 4; i += blockDim.x)
        ((float4*)sW)[i] = ((const float4*)W1)[i];
    __syncthreads();

    int t = blockIdx.x * blockDim.x + threadIdx.x;
    size_t r0 = (size_t)t * 2;
    if (r0 >= N_NODES) return;

    unsigned long long acc[2][8];
#pragma unroll
    for (int m = 0; m < 2; m++)
#pragma unroll
        for (int j = 0; j < 8; j++) acc[m][j] = 0ull;

    const float* xb = x + r0 * F_IN;

    for (int k = 0; k < F_IN; k += 4) {
        float4 xv0 = __ldg((const float4*)(xb + k));
        float4 xv1 = __ldg((const float4*)(xb + F_IN + k));
#pragma unroll
        for (int kk = 0; kk < 4; kk++) {
            const unsigned long long* wp =
                (const unsigned long long*)(sW + (k + kk) * 16);
            unsigned long long w0 = wp[0], w1 = wp[1], w2 = wp[2], w3 = wp[3];
            unsigned long long w4 = wp[4], w5 = wp[5], w6 = wp[6], w7 = wp[7];
            float xs0 = (kk == 0) ? xv0.x : (kk == 1) ? xv0.y : (kk == 2) ? xv0.z : xv0.w;
            float xs1 = (kk == 0) ? xv1.x : (kk == 1) ? xv1.y : (kk == 2) ? xv1.z : xv1.w;
            unsigned long long xp0 = bcast2(xs0);
            unsigned long long xp1 = bcast2(xs1);
            ffma2(acc[0][0], xp0, w0); ffma2(acc[0][1], xp0, w1);
            ffma2(acc[0][2], xp0, w2); ffma2(acc[0][3], xp0, w3);
            ffma2(acc[0][4], xp0, w4); ffma2(acc[0][5], xp0, w5);
            ffma2(acc[0][6], xp0, w6); ffma2(acc[0][7], xp0, w7);
            ffma2(acc[1][0], xp1, w0); ffma2(acc[1][1], xp1, w1);
            ffma2(acc[1][2], xp1, w2); ffma2(acc[1][3], xp1, w3);
            ffma2(acc[1][4], xp1, w4); ffma2(acc[1][5], xp1, w5);
            ffma2(acc[1][6], xp1, w6); ffma2(acc[1][7], xp1, w7);
        }
    }

#pragma unroll
    for (int m = 0; m < 2; m++) {
        if (r0 + m >= N_NODES) break;
        __half2 hs[8];
#pragma unroll
        for (int j = 0; j < 8; j++) {
            float lo, hi;
            asm("mov.b64 {%0, %1}, %2;" : "=f"(lo), "=f"(hi) : "l"(acc[m][j]));
            hs[j] = __floats2half2_rn(lo, hi);
        }
        float4* dst = (float4*)(g_ph + (r0 + m) * 8);
        dst[0] = *(float4*)&hs[0];
        dst[1] = *(float4*)&hs[4];
    }
}

// ---------------- fused dinv + scale: one node pass ------------------------
__global__ void k_dinvscale() {
    int i = blockIdx.x * blockDim.x + threadIdx.x;
    if (i >= N_NODES) return;
    float d = rsqrtf((float)(g_cnt[i] + 1));   // +1 self-loop
    g_dinv[i] = d;
    float4* row = (float4*)(g_ph + (size_t)i * 8);
#pragma unroll
    for (int c = 0; c < 2; c++) {
        float4 raw = row[c];
        __half2* h = (__half2*)&raw;
#pragma unroll
        for (int k = 0; k < 4; k++) {
            float2 f = __half22float2(h[k]);
            h[k] = __floats2half2_rn(f.x * d, f.y * d);
        }
        row[c] = raw;
    }
}

// ---------------- half-quad fp16 gather: 8 threads/node -------------------
__device__ __forceinline__ float4 gather_sum8h(const __half2* __restrict__ src,
                                               const int* __restrict__ slots,
                                               int cnt, int q, int half) {
    float4 a0 = make_float4(0.f, 0.f, 0.f, 0.f);
    float4 a1 = make_float4(0.f, 0.f, 0.f, 0.f);
    int e = 2 * half;
    for (; e + 2 <= cnt; e += 4) {
        int r0 = __ldg(&slots[e]);
        int r1 = __ldg(&slots[e + 1]);
        uint2 b0 = __ldg((const uint2*)(src + (size_t)r0 * 8 + q * 2));
        uint2 b1 = __ldg((const uint2*)(src + (size_t)r1 * 8 + q * 2));
        float2 l00 = __half22float2(*(__half2*)&b0.x);
        float2 l01 = __half22float2(*(__half2*)&b0.y);
        float2 l10 = __half22float2(*(__half2*)&b1.x);
        float2 l11 = __half22float2(*(__half2*)&b1.y);
        a0.x += l00.x; a0.y += l00.y; a0.z += l01.x; a0.w += l01.y;
        a1.x += l10.x; a1.y += l10.y; a1.z += l11.x; a1.w += l11.y;
    }
    if (e < cnt) {
        int r0 = __ldg(&slots[e]);
        uint2 b0 = __ldg((const uint2*)(src + (size_t)r0 * 8 + q * 2));
        float2 l00 = __half22float2(*(__half2*)&b0.x);
        float2 l01 = __half22float2(*(__half2*)&b0.y);
        a0.x += l00.x; a0.y += l00.y; a0.z += l01.x; a0.w += l01.y;
    }
    float4 r;
    r.x = a0.x + a1.x; r.y = a0.y + a1.y;
    r.z = a0.z + a1.z; r.w = a0.w + a1.w;
    r.x += __shfl_xor_sync(0xffffffffu, r.x, 4);
    r.y += __shfl_xor_sync(0xffffffffu, r.y, 4);
    r.z += __shfl_xor_sync(0xffffffffu, r.z, 4);
    r.w += __shfl_xor_sync(0xffffffffu, r.w, 4);
    return r;
}

__device__ __forceinline__ float4 load_quad_h(const __half2* __restrict__ src,
                                              int node, int q) {
    uint2 b = __ldg((const uint2*)(src + (size_t)node * 8 + q * 2));
    float2 lo = __half22float2(*(__half2*)&b.x);
    float2 hi = __half22float2(*(__half2*)&b.y);
    return make_float4(lo.x, lo.y, hi.x, hi.y);
}

// ---------------- fused agg1 + relu + layer-2 linear ----------------------
__global__ __launch_bounds__(128) void k_agg_l2(const float* __restrict__ b1,
                                                const float* __restrict__ W2) {
    __shared__ float sW2[HID * 16];
    if (threadIdx.x < 64)
        ((float4*)sW2)[threadIdx.x] = ((const float4*)W2)[threadIdx.x];
    __syncthreads();

    int t = blockIdx.x * blockDim.x + threadIdx.x;
    int node = t >> 3;
    int q    = t & 3;
    int half = (t >> 2) & 1;
    bool valid = node < N_NODES;

    int cnt = 0;
    if (valid) cnt = min(g_cnt[node], SLOT_CAP);
    const int* slots = g_slots + (size_t)(valid ? node : 0) * SLOT_CAP;

    float4 a = gather_sum8h(g_ph, slots, cnt, q, half);

    float d = valid ? g_dinv[node] : 0.f;
    float4 ps = valid ? load_quad_h(g_ph, node, q)
                      : make_float4(0.f, 0.f, 0.f, 0.f);
    float4 bq = __ldg((const float4*)b1 + q);

    float tq[4];
    tq[0] = fmaxf((a.x + ps.x) * d + bq.x, 0.f);
    tq[1] = fmaxf((a.y + ps.y) * d + bq.y, 0.f);
    tq[2] = fmaxf((a.z + ps.z) * d + bq.z, 0.f);
    tq[3] = fmaxf((a.w + ps.w) * d + bq.w, 0.f);

    // 16x16 GEMM across the group-of-4 (both halves redundantly)
    float o[4] = {0.f, 0.f, 0.f, 0.f};
#pragma unroll
    for (int r = 0; r < 4; r++) {
        float tv0 = __shfl_xor_sync(0xffffffffu, tq[0], r);
        float tv1 = __shfl_xor_sync(0xffffffffu, tq[1], r);
        float tv2 = __shfl_xor_sync(0xffffffffu, tq[2], r);
        float tv3 = __shfl_xor_sync(0xffffffffu, tq[3], r);
        int g = (q ^ r) * 4;
        const float* w0 = sW2 + (g + 0) * 16 + q * 4;
        const float* w1 = sW2 + (g + 1) * 16 + q * 4;
        const float* w2 = sW2 + (g + 2) * 16 + q * 4;
        const float* w3 = sW2 + (g + 3) * 16 + q * 4;
#pragma unroll
        for (int c = 0; c < 4; c++)
            o[c] += tv0 * w0[c] + tv1 * w1[c] + tv2 * w2[c] + tv3 * w3[c];
    }

    if (valid && half == 0) {
        __half2 hs[2];
        hs[0] = __floats2half2_rn(o[0] * d, o[1] * d);
        hs[1] = __floats2half2_rn(o[2] * d, o[3] * d);
        *(float2*)(g_ph2 + (size_t)node * 8 + q * 2) = *(float2*)&hs[0];
    }
}

// ---------------- fused agg2 + bias + log_softmax -------------------------
__global__ __launch_bounds__(128) void k_agg_final(const float* __restrict__ b2,
                                                   float* __restrict__ out) {
    int t = blockIdx.x * blockDim.x + threadIdx.x;
    int node = t >> 3;
    int q    = t & 3;
    int half = (t >> 2) & 1;
    bool valid = node < N_NODES;

    int cnt = 0;
    if (valid) cnt = min(g_cnt[node], SLOT_CAP);
    const int* slots = g_slots + (size_t)(valid ? node : 0) * SLOT_CAP;

    float4 a = gather_sum8h(g_ph2, slots, cnt, q, half);

    float d = valid ? g_dinv[node] : 0.f;
    float4 ps = valid ? load_quad_h(g_ph2, node, q)
                      : make_float4(0.f, 0.f, 0.f, 0.f);
    float4 bq = __ldg((const float4*)b2 + q);

    float l[4];
    l[0] = (a.x + ps.x) * d + bq.x;
    l[1] = (a.y + ps.y) * d + bq.y;
    l[2] = (a.z + ps.z) * d + bq.z;
    l[3] = (a.w + ps.w) * d + bq.w;

    // log-softmax across the group-of-4 (both halves redundantly)
    float m = fmaxf(fmaxf(l[0], l[1]), fmaxf(l[2], l[3]));
    m = fmaxf(m, __shfl_xor_sync(0xffffffffu, m, 1));
    m = fmaxf(m, __shfl_xor_sync(0xffffffffu, m, 2));
    float s = expf(l[0] - m) + expf(l[1] - m) + expf(l[2] - m) + expf(l[3] - m);
    s += __shfl_xor_sync(0xffffffffu, s, 1);
    s += __shfl_xor_sync(0xffffffffu, s, 2);
    float lse = m + logf(s);

    if (valid && half == 0) {
        float4 v;
        v.x = l[0] - lse; v.y = l[1] - lse; v.z = l[2] - lse; v.w = l[3] - lse;
        ((float4*)(out + (size_t)node * HID))[q] = v;
    }
}

// ---------------- host orchestration -------------------------------------
// main:  memset(g_cnt) -> [wait detect] -> fill -> [wait gemm1] -> dinvscale
//        -> agg_l2 -> agg_final
// side:  detect -> gemm1
extern "C" void kernel_launch(void* const* d_in, const int* in_sizes, int n_in,
                              void* d_out, int out_size) {
    const float* x  = (const float*)d_in[0];
    const int*   ei = (const int*)d_in[1];
    const float* W1 = (const float*)d_in[2];
    const float* b1 = (const float*)d_in[3];
    const float* W2 = (const float*)d_in[4];
    const float* b2 = (const float*)d_in[5];
    float* out = (float*)d_out;

    const int TB  = 256;
    const int TBA = 128;
    int grid_nodes = (N_NODES + TB - 1) / TB;
    int grid_edges = (N_EDGES + TB - 1) / TB;
    int grid_gemm  = ((N_NODES + 1) / 2 + TB - 1) / TB;
    int grid_agg   = ((size_t)N_NODES * 8 + TBA - 1) / TBA;

    void* cnt_ptr = nullptr;
    cudaGetSymbolAddress(&cnt_ptr, g_cnt);

    cudaStream_t s2;
    cudaEvent_t evFork, evDetect, evGemm;
    cudaStreamCreateWithFlags(&s2, cudaStreamNonBlocking);
    cudaEventCreateWithFlags(&evFork, cudaEventDisableTiming);
    cudaEventCreateWithFlags(&evDetect, cudaEventDisableTiming);
    cudaEventCreateWithFlags(&evGemm, cudaEventDisableTiming);

    // fork: detect + GEMM1 on side stream
    cudaEventRecord(evFork, 0);
    cudaStreamWaitEvent(s2, evFork, 0);
    k_detect<<<1, 256, 0, s2>>>(ei);
    cudaEventRecord(evDetect, s2);
    k_gemm1<<<grid_gemm, TB, 0, s2>>>(x, W1);
    cudaEventRecord(evGemm, s2);

    // main: zero counts via graph memset, then fill (needs g_is64)
    cudaMemsetAsync(cnt_ptr, 0, N_NODES * sizeof(int), 0);
    cudaStreamWaitEvent(0, evDetect, 0);
    k_fill<<<grid_edges, TB>>>(ei);

    // join: dinvscale needs final counts + gemm1 output
    cudaStreamWaitEvent(0, evGemm, 0);
    k_dinvscale<<<grid_nodes, TB>>>();

    k_agg_l2   <<<grid_agg, TBA>>>(b1, W2);
    k_agg_final<<<grid_agg, TBA>>>(b2, out);

    cudaStreamDestroy(s2);
    cudaEventDestroy(evFork);
    cudaEventDestroy(evDetect);
    cudaEventDestroy(evGemm);
}

// round 15
// speedup vs baseline: 1.0133x; 1.0133x over previous
#include <cuda_runtime.h>
#include <cuda_fp16.h>

// GCN 2-layer forward, fixed shape.  (R13 config + int2 slot loads)
// Slot-bucketed aggregation, f32x2 GEMM, fp16 inter-layer features,
// fused epilogues, 8 threads/node agg, fused dinv+scale, 2-stream overlap.
#define N_NODES 100000
#define N_EDGES 3200000
#define F_IN    512
#define HID     16
#define SLOT_CAP 128           // max degree capacity (Poisson(32), max~60)

// ---------------- device scratch (no allocations allowed) ----------------
__device__ int   g_is64;
__device__ int   g_cnt  [N_NODES];            // per-node incoming-edge count
__device__ __align__(16) int g_slots[(size_t)N_NODES * SLOT_CAP]; // row ids per col
__device__ float g_dinv [N_NODES];
__device__ __align__(16) __half2 g_ph [N_NODES * 8];  // layer-1 feats (8 half2/row)
__device__ __align__(16) __half2 g_ph2[N_NODES * 8];  // layer-2 feats

// ---------------- init: zero counts + detect edge dtype -------------------
__global__ void k_init(const int* __restrict__ e) {
    int i = blockIdx.x * blockDim.x + threadIdx.x;
    if (i < N_NODES) g_cnt[i] = 0;
    if (blockIdx.x == 0) {
        // int64 little-endian values < 2^31 -> odd words all zero
        int odd = e[2 * threadIdx.x + 1];
        int any = __syncthreads_or(odd != 0);
        if (threadIdx.x == 0) g_is64 = !any;
    }
}

// ---------------- slot fill: one pass, scalar per edge --------------------
__global__ void k_fill(const int* __restrict__ e) {
    int i = blockIdx.x * blockDim.x + threadIdx.x;
    if (i >= N_EDGES) return;
    int r, c;
    if (g_is64) {
        r = (int)((const long long*)e)[i];
        c = (int)((const long long*)e)[(long long)N_EDGES + i];
    } else {
        r = e[i];
        c = e[N_EDGES + i];
    }
    int pos = atomicAdd(&g_cnt[c], 1);
    if (pos < SLOT_CAP)
        g_slots[(size_t)c * SLOT_CAP + pos] = r;
}

// ---------------- GEMM1: ph = half(x @ W1) (unscaled), f32x2 FMA ----------
__device__ __forceinline__ void ffma2(unsigned long long& acc,
                                      unsigned long long a,
                                      unsigned long long b) {
    asm("fma.rn.f32x2 %0, %1, %2, %0;" : "+l"(acc) : "l"(a), "l"(b));
}

__device__ __forceinline__ unsigned long long bcast2(float x) {
    unsigned long long r;
    asm("mov.b64 %0, {%1, %1};" : "=l"(r) : "f"(x));
    return r;
}

__global__ __launch_bounds__(256) void k_gemm1(const float* __restrict__ x,
                                               const float* __restrict__ W1) {
    __shared__ float sW[F_IN * HID];   // 32 KB
    for (int i = threadIdx.x; i < (F_IN * HID) / 4; i += blockDim.x)
        ((float4*)sW)[i] = ((const float4*)W1)[i];
    __syncthreads();

    int t = blockIdx.x * blockDim.x + threadIdx.x;
    size_t r0 = (size_t)t * 2;
    if (r0 >= N_NODES) return;

    unsigned long long acc[2][8];
#pragma unroll
    for (int m = 0; m < 2; m++)
#pragma unroll
        for (int j = 0; j < 8; j++) acc[m][j] = 0ull;

    const float* xb = x + r0 * F_IN;

    for (int k = 0; k < F_IN; k += 4) {
        float4 xv0 = __ldg((const float4*)(xb + k));
        float4 xv1 = __ldg((const float4*)(xb + F_IN + k));
#pragma unroll
        for (int kk = 0; kk < 4; kk++) {
            const unsigned long long* wp =
                (const unsigned long long*)(sW + (k + kk) * 16);
            unsigned long long w0 = wp[0], w1 = wp[1], w2 = wp[2], w3 = wp[3];
            unsigned long long w4 = wp[4], w5 = wp[5], w6 = wp[6], w7 = wp[7];
            float xs0 = (kk == 0) ? xv0.x : (kk == 1) ? xv0.y : (kk == 2) ? xv0.z : xv0.w;
            float xs1 = (kk == 0) ? xv1.x : (kk == 1) ? xv1.y : (kk == 2) ? xv1.z : xv1.w;
            unsigned long long xp0 = bcast2(xs0);
            unsigned long long xp1 = bcast2(xs1);
            ffma2(acc[0][0], xp0, w0); ffma2(acc[0][1], xp0, w1);
            ffma2(acc[0][2], xp0, w2); ffma2(acc[0][3], xp0, w3);
            ffma2(acc[0][4], xp0, w4); ffma2(acc[0][5], xp0, w5);
            ffma2(acc[0][6], xp0, w6); ffma2(acc[0][7], xp0, w7);
            ffma2(acc[1][0], xp1, w0); ffma2(acc[1][1], xp1, w1);
            ffma2(acc[1][2], xp1, w2); ffma2(acc[1][3], xp1, w3);
            ffma2(acc[1][4], xp1, w4); ffma2(acc[1][5], xp1, w5);
            ffma2(acc[1][6], xp1, w6); ffma2(acc[1][7], xp1, w7);
        }
    }

#pragma unroll
    for (int m = 0; m < 2; m++) {
        if (r0 + m >= N_NODES) break;
        __half2 hs[8];
#pragma unroll
        for (int j = 0; j < 8; j++) {
            float lo, hi;
            asm("mov.b64 {%0, %1}, %2;" : "=f"(lo), "=f"(hi) : "l"(acc[m][j]));
            hs[j] = __floats2half2_rn(lo, hi);
        }
        float4* dst = (float4*)(g_ph + (r0 + m) * 8);
        dst[0] = *(float4*)&hs[0];
        dst[1] = *(float4*)&hs[4];
    }
}

// ---------------- fused dinv + scale: one node pass ------------------------
__global__ void k_dinvscale() {
    int i = blockIdx.x * blockDim.x + threadIdx.x;
    if (i >= N_NODES) return;
    float d = rsqrtf((float)(g_cnt[i] + 1));   // +1 self-loop
    g_dinv[i] = d;
    float4* row = (float4*)(g_ph + (size_t)i * 8);
#pragma unroll
    for (int c = 0; c < 2; c++) {
        float4 raw = row[c];
        __half2* h = (__half2*)&raw;
#pragma unroll
        for (int k = 0; k < 4; k++) {
            float2 f = __half22float2(h[k]);
            h[k] = __floats2half2_rn(f.x * d, f.y * d);
        }
        row[c] = raw;
    }
}

// ---------------- half-quad fp16 gather: 8 threads/node -------------------
// Slot pairs are loaded as one 8B int2 (e always even -> aligned), halving
// index-LDG issue count vs two scalar loads. Feature loads unchanged.
__device__ __forceinline__ float4 gather_sum8h(const __half2* __restrict__ src,
                                               const int* __restrict__ slots,
                                               int cnt, int q, int half) {
    float4 a0 = make_float4(0.f, 0.f, 0.f, 0.f);
    float4 a1 = make_float4(0.f, 0.f, 0.f, 0.f);
    int e = 2 * half;
    for (; e + 2 <= cnt; e += 4) {
        int2 rp = __ldg((const int2*)(slots + e));
        uint2 b0 = __ldg((const uint2*)(src + (size_t)rp.x * 8 + q * 2));
        uint2 b1 = __ldg((const uint2*)(src + (size_t)rp.y * 8 + q * 2));
        float2 l00 = __half22float2(*(__half2*)&b0.x);
        float2 l01 = __half22float2(*(__half2*)&b0.y);
        float2 l10 = __half22float2(*(__half2*)&b1.x);
        float2 l11 = __half22float2(*(__half2*)&b1.y);
        a0.x += l00.x; a0.y += l00.y; a0.z += l01.x; a0.w += l01.y;
        a1.x += l10.x; a1.y += l10.y; a1.z += l11.x; a1.w += l11.y;
    }
    if (e < cnt) {
        int r0 = __ldg(&slots[e]);
        uint2 b0 = __ldg((const uint2*)(src + (size_t)r0 * 8 + q * 2));
        float2 l00 = __half22float2(*(__half2*)&b0.x);
        float2 l01 = __half22float2(*(__half2*)&b0.y);
        a0.x += l00.x; a0.y += l00.y; a0.z += l01.x; a0.w += l01.y;
    }
    float4 r;
    r.x = a0.x + a1.x; r.y = a0.y + a1.y;
    r.z = a0.z + a1.z; r.w = a0.w + a1.w;
    r.x += __shfl_xor_sync(0xffffffffu, r.x, 4);
    r.y += __shfl_xor_sync(0xffffffffu, r.y, 4);
    r.z += __shfl_xor_sync(0xffffffffu, r.z, 4);
    r.w += __shfl_xor_sync(0xffffffffu, r.w, 4);
    return r;
}

__device__ __forceinline__ float4 load_quad_h(const __half2* __restrict__ src,
                                              int node, int q) {
    uint2 b = __ldg((const uint2*)(src + (size_t)node * 8 + q * 2));
    float2 lo = __half22float2(*(__half2*)&b.x);
    float2 hi = __half22float2(*(__half2*)&b.y);
    return make_float4(lo.x, lo.y, hi.x, hi.y);
}

// ---------------- fused agg1 + relu + layer-2 linear ----------------------
__global__ __launch_bounds__(256) void k_agg_l2(const float* __restrict__ b1,
                                                const float* __restrict__ W2) {
    __shared__ float sW2[HID * 16];
    if (threadIdx.x < 64)
        ((float4*)sW2)[threadIdx.x] = ((const float4*)W2)[threadIdx.x];
    __syncthreads();

    int t = blockIdx.x * blockDim.x + threadIdx.x;
    int node = t >> 3;
    int q    = t & 3;
    int half = (t >> 2) & 1;
    bool valid = node < N_NODES;

    int cnt = 0;
    if (valid) cnt = min(g_cnt[node], SLOT_CAP);
    const int* slots = g_slots + (size_t)(valid ? node : 0) * SLOT_CAP;

    float4 a = gather_sum8h(g_ph, slots, cnt, q, half);

    float d = valid ? g_dinv[node] : 0.f;
    float4 ps = valid ? load_quad_h(g_ph, node, q)
                      : make_float4(0.f, 0.f, 0.f, 0.f);
    float4 bq = __ldg((const float4*)b1 + q);

    float tq[4];
    tq[0] = fmaxf((a.x + ps.x) * d + bq.x, 0.f);
    tq[1] = fmaxf((a.y + ps.y) * d + bq.y, 0.f);
    tq[2] = fmaxf((a.z + ps.z) * d + bq.z, 0.f);
    tq[3] = fmaxf((a.w + ps.w) * d + bq.w, 0.f);

    // 16x16 GEMM across the group-of-4 (both halves redundantly)
    float o[4] = {0.f, 0.f, 0.f, 0.f};
#pragma unroll
    for (int r = 0; r < 4; r++) {
        float tv0 = __shfl_xor_sync(0xffffffffu, tq[0], r);
        float tv1 = __shfl_xor_sync(0xffffffffu, tq[1], r);
        float tv2 = __shfl_xor_sync(0xffffffffu, tq[2], r);
        float tv3 = __shfl_xor_sync(0xffffffffu, tq[3], r);
        int g = (q ^ r) * 4;
        const float* w0 = sW2 + (g + 0) * 16 + q * 4;
        const float* w1 = sW2 + (g + 1) * 16 + q * 4;
        const float* w2 = sW2 + (g + 2) * 16 + q * 4;
        const float* w3 = sW2 + (g + 3) * 16 + q * 4;
#pragma unroll
        for (int c = 0; c < 4; c++)
            o[c] += tv0 * w0[c] + tv1 * w1[c] + tv2 * w2[c] + tv3 * w3[c];
    }

    if (valid && half == 0) {
        __half2 hs[2];
        hs[0] = __floats2half2_rn(o[0] * d, o[1] * d);
        hs[1] = __floats2half2_rn(o[2] * d, o[3] * d);
        *(float2*)(g_ph2 + (size_t)node * 8 + q * 2) = *(float2*)&hs[0];
    }
}

// ---------------- fused agg2 + bias + log_softmax -------------------------
__global__ __launch_bounds__(256) void k_agg_final(const float* __restrict__ b2,
                                                   float* __restrict__ out) {
    int t = blockIdx.x * blockDim.x + threadIdx.x;
    int node = t >> 3;
    int q    = t & 3;
    int half = (t >> 2) & 1;
    bool valid = node < N_NODES;

    int cnt = 0;
    if (valid) cnt = min(g_cnt[node], SLOT_CAP);
    const int* slots = g_slots + (size_t)(valid ? node : 0) * SLOT_CAP;

    float4 a = gather_sum8h(g_ph2, slots, cnt, q, half);

    float d = valid ? g_dinv[node] : 0.f;
    float4 ps = valid ? load_quad_h(g_ph2, node, q)
                      : make_float4(0.f, 0.f, 0.f, 0.f);
    float4 bq = __ldg((const float4*)b2 + q);

    float l[4];
    l[0] = (a.x + ps.x) * d + bq.x;
    l[1] = (a.y + ps.y) * d + bq.y;
    l[2] = (a.z + ps.z) * d + bq.z;
    l[3] = (a.w + ps.w) * d + bq.w;

    // log-softmax across the group-of-4 (both halves redundantly)
    float m = fmaxf(fmaxf(l[0], l[1]), fmaxf(l[2], l[3]));
    m = fmaxf(m, __shfl_xor_sync(0xffffffffu, m, 1));
    m = fmaxf(m, __shfl_xor_sync(0xffffffffu, m, 2));
    float s = expf(l[0] - m) + expf(l[1] - m) + expf(l[2] - m) + expf(l[3] - m);
    s += __shfl_xor_sync(0xffffffffu, s, 1);
    s += __shfl_xor_sync(0xffffffffu, s, 2);
    float lse = m + logf(s);

    if (valid && half == 0) {
        float4 v;
        v.x = l[0] - lse; v.y = l[1] - lse; v.z = l[2] - lse; v.w = l[3] - lse;
        ((float4*)(out + (size_t)node * HID))[q] = v;
    }
}

// ---------------- host orchestration -------------------------------------
// main:  init -> fill -> [join gemm1] -> dinvscale -> agg_l2 -> agg_final
// side:  gemm1
extern "C" void kernel_launch(void* const* d_in, const int* in_sizes, int n_in,
                              void* d_out, int out_size) {
    const float* x  = (const float*)d_in[0];
    const int*   ei = (const int*)d_in[1];
    const float* W1 = (const float*)d_in[2];
    const float* b1 = (const float*)d_in[3];
    const float* W2 = (const float*)d_in[4];
    const float* b2 = (const float*)d_in[5];
    float* out = (float*)d_out;

    const int TB = 256;
    int grid_nodes = (N_NODES + TB - 1) / TB;
    int grid_edges = (N_EDGES + TB - 1) / TB;
    int grid_gemm  = ((N_NODES + 1) / 2 + TB - 1) / TB;
    int grid_agg   = ((size_t)N_NODES * 8 + TB - 1) / TB;

    cudaStream_t s2;
    cudaEvent_t evFork, evGemm;
    cudaStreamCreateWithFlags(&s2, cudaStreamNonBlocking);
    cudaEventCreateWithFlags(&evFork, cudaEventDisableTiming);
    cudaEventCreateWithFlags(&evGemm, cudaEventDisableTiming);

    // fork: GEMM1 on side stream (hidden under fill)
    cudaEventRecord(evFork, 0);
    cudaStreamWaitEvent(s2, evFork, 0);
    k_gemm1<<<grid_gemm, TB, 0, s2>>>(x, W1);
    cudaEventRecord(evGemm, s2);

    // main: edge bucketing pipeline
    k_init<<<grid_nodes, TB>>>(ei);
    k_fill<<<grid_edges, TB>>>(ei);

    // join: dinvscale needs final counts + gemm1 output
    cudaStreamWaitEvent(0, evGemm, 0);
    k_dinvscale<<<grid_nodes, TB>>>();

    k_agg_l2   <<<grid_agg, TB>>>(b1, W2);
    k_agg_final<<<grid_agg, TB>>>(b2, out);

    cudaStreamDestroy(s2);
    cudaEventDestroy(evFork);
    cudaEventDestroy(evGemm);
}